// round 2
// baseline (speedup 1.0000x reference)
#include <cuda_runtime.h>

#define BB 64
#define NN 65536
#define NP 4
#define RADIUS 0.2f
#define THREADS_FPS 1024

// Scratch (allocation-free rule: __device__ globals)
__device__ float g_xyz[(size_t)BB * NN * 3];   // packed xyz, 48 MB
__device__ int   g_kept[(size_t)BB * NN];      // stable kept indices, 16 MB
__device__ int   g_numvalid[BB];

// ---------------------------------------------------------------------------
// K1: pack xyz (stride-6 -> stride-3) so the 4 FPS sweeps read 12B/pt from L2
// ---------------------------------------------------------------------------
__global__ void pack_xyz_kernel(const float* __restrict__ pts) {
    int i = blockIdx.x * blockDim.x + threadIdx.x;
    if (i >= BB * NN) return;
    const float* p = pts + (size_t)i * 6;
    float* o = g_xyz + (size_t)i * 3;
    o[0] = p[0];
    o[1] = p[1];
    o[2] = p[2];
}

// ---------------------------------------------------------------------------
// K2: per-batch FPS (4 centers, start at idx 0) + keep mask + stable compact.
// One block of 1024 threads per batch.
// ---------------------------------------------------------------------------
__global__ void __launch_bounds__(THREADS_FPS) fps_compact_kernel() {
    const int b = blockIdx.x;
    const int tid = threadIdx.x;
    const float* __restrict__ xyz = g_xyz + (size_t)b * NN * 3;

    __shared__ float sc[NP][3];           // centers
    __shared__ float s_val[32];
    __shared__ int   s_idx[32];
    __shared__ unsigned s_bm[NN / 32];    // 8 KB keep bitmask
    __shared__ int   s_ws[32];            // warp scan sums

    if (tid == 0) {
        sc[0][0] = xyz[0]; sc[0][1] = xyz[1]; sc[0][2] = xyz[2];
    }
    __syncthreads();

    // ---- FPS: 3 argmax passes (centers 1..3) ----
    for (int s = 1; s < NP; s++) {
        float best = -1.0f;
        int bidx = NN;
        for (int p = tid; p < NN; p += THREADS_FPS) {
            float x = xyz[3 * p], y = xyz[3 * p + 1], z = xyz[3 * p + 2];
            float m = 1e10f;
            #pragma unroll
            for (int t = 0; t < NP - 1; t++) {
                if (t < s) {
                    float dx = x - sc[t][0];
                    float dy = y - sc[t][1];
                    float dz = z - sc[t][2];
                    float d = dx * dx + dy * dy + dz * dz;
                    m = fminf(m, d);
                }
            }
            // first-occurrence argmax: larger value wins; tie -> smaller index
            if (m > best || (m == best && p < bidx)) { best = m; bidx = p; }
        }
        // warp reduce
        #pragma unroll
        for (int off = 16; off; off >>= 1) {
            float ov = __shfl_down_sync(0xffffffffu, best, off);
            int   oi = __shfl_down_sync(0xffffffffu, bidx, off);
            if (ov > best || (ov == best && oi < bidx)) { best = ov; bidx = oi; }
        }
        if ((tid & 31) == 0) { s_val[tid >> 5] = best; s_idx[tid >> 5] = bidx; }
        __syncthreads();
        if (tid < 32) {
            best = s_val[tid]; bidx = s_idx[tid];
            #pragma unroll
            for (int off = 16; off; off >>= 1) {
                float ov = __shfl_down_sync(0xffffffffu, best, off);
                int   oi = __shfl_down_sync(0xffffffffu, bidx, off);
                if (ov > best || (ov == best && oi < bidx)) { best = ov; bidx = oi; }
            }
            if (tid == 0) {
                sc[s][0] = xyz[3 * bidx];
                sc[s][1] = xyz[3 * bidx + 1];
                sc[s][2] = xyz[3 * bidx + 2];
            }
        }
        __syncthreads();
    }

    // ---- keep pass: ballot into smem bitmask (coalesced, stride-1024) ----
    for (int p = tid; p < NN; p += THREADS_FPS) {
        float x = xyz[3 * p], y = xyz[3 * p + 1], z = xyz[3 * p + 2];
        float m = 1e10f;
        #pragma unroll
        for (int t = 0; t < NP; t++) {
            float dx = x - sc[t][0];
            float dy = y - sc[t][1];
            float dz = z - sc[t][2];
            float d = dx * dx + dy * dy + dz * dz;
            m = fminf(m, d);
        }
        bool keep = (sqrtf(m) >= RADIUS);   // matches norm(..) >= 0.2 (sqrt monotone)
        unsigned msk = __ballot_sync(0xffffffffu, keep);
        if ((tid & 31) == 0) s_bm[p >> 5] = msk;
    }
    __syncthreads();

    // ---- stable compaction: block exclusive scan over popcounts ----
    const int w0 = tid * 2;
    const int w1 = tid * 2 + 1;
    int cnt = __popc(s_bm[w0]) + __popc(s_bm[w1]);

    int lane = tid & 31, warp = tid >> 5;
    int inc = cnt;
    #pragma unroll
    for (int off = 1; off < 32; off <<= 1) {
        int n = __shfl_up_sync(0xffffffffu, inc, off);
        if (lane >= off) inc += n;
    }
    if (lane == 31) s_ws[warp] = inc;
    __syncthreads();
    if (warp == 0) {
        int v = s_ws[lane];
        #pragma unroll
        for (int off = 1; off < 32; off <<= 1) {
            int n = __shfl_up_sync(0xffffffffu, v, off);
            if (lane >= off) v += n;
        }
        s_ws[lane] = v;
    }
    __syncthreads();
    int excl = inc - cnt + (warp ? s_ws[warp - 1] : 0);
    int total = s_ws[31];

    // emit kept indices in ascending order
    int off = excl;
    int* kept = g_kept + (size_t)b * NN;
    {
        unsigned m = s_bm[w0];
        int base = w0 * 32;
        while (m) { int j = __ffs(m) - 1; m &= m - 1; kept[off++] = base + j; }
        m = s_bm[w1];
        base = w1 * 32;
        while (m) { int j = __ffs(m) - 1; m &= m - 1; kept[off++] = base + j; }
    }
    if (tid == 0) g_numvalid[b] = total;
}

// ---------------------------------------------------------------------------
// K3: gather output: out[b,j] = points[b, kept[j % nv]]  (zeros if nv==0)
// ---------------------------------------------------------------------------
__global__ void gather_kernel(const float* __restrict__ pts,
                              float* __restrict__ out) {
    int i = blockIdx.x * blockDim.x + threadIdx.x;
    if (i >= BB * NN) return;
    int b = i >> 16;           // N = 65536
    int j = i & (NN - 1);
    int nv = g_numvalid[b];
    float2* o = (float2*)(out + (size_t)i * 6);
    if (nv == 0) {
        float2 z = make_float2(0.f, 0.f);
        o[0] = z; o[1] = z; o[2] = z;
        return;
    }
    int k = (j < nv) ? j : (j % nv);
    int src = g_kept[(size_t)b * NN + k];
    const float2* s = (const float2*)(pts + ((size_t)b * NN + src) * 6);
    float2 a0 = s[0], a1 = s[1], a2 = s[2];
    o[0] = a0; o[1] = a1; o[2] = a2;
}

extern "C" void kernel_launch(void* const* d_in, const int* in_sizes, int n_in,
                              void* d_out, int out_size) {
    const float* pts = (const float*)d_in[0];
    float* out = (float*)d_out;
    (void)in_sizes; (void)n_in; (void)out_size;

    pack_xyz_kernel<<<(BB * NN + 255) / 256, 256>>>(pts);
    fps_compact_kernel<<<BB, THREADS_FPS>>>();
    gather_kernel<<<(BB * NN + 255) / 256, 256>>>(pts, out);
}

// round 4
// speedup vs baseline: 1.1576x; 1.1576x over previous
#include <cuda_runtime.h>

#define BB 64
#define NN 65536
#define RADIUS 0.2f

// Scratch (__device__ globals per allocation-free rule)
__device__ float4   g_xyz4[(size_t)BB * NN];        // packed xyz, 64 MB
__device__ float    g_pval[3][BB * 64];             // argmax partials per FPS step
__device__ int      g_pidx[3][BB * 64];
__device__ unsigned g_bm[BB * (NN / 32)];           // keep bitmask, 512 KB
__device__ int      g_cnt[BB * 32];                 // per-chunk keep counts
__device__ int      g_numvalid[BB];
__device__ int      g_kept[(size_t)BB * NN];        // stable kept indices, 16 MB

// ---------------------------------------------------------------------------
// Argmax helpers: larger value wins, tie -> smaller index (jnp.argmax semantics)
// ---------------------------------------------------------------------------
__device__ __forceinline__ void warp_argmax(float& v, int& i) {
    #pragma unroll
    for (int off = 16; off; off >>= 1) {
        float ov = __shfl_down_sync(0xffffffffu, v, off);
        int   oi = __shfl_down_sync(0xffffffffu, i, off);
        if (ov > v || (ov == v && oi < i)) { v = ov; i = oi; }
    }
}

// 256-thread (8-warp) block argmax; result valid in thread 0.
__device__ __forceinline__ void block_argmax256(float& v, int& i, int tid,
                                                float* s_val, int* s_idx) {
    warp_argmax(v, i);
    if ((tid & 31) == 0) { s_val[tid >> 5] = v; s_idx[tid >> 5] = i; }
    __syncthreads();
    if (tid < 32) {
        v = (tid < 8) ? s_val[tid] : -2.0f;
        i = (tid < 8) ? s_idx[tid] : NN;
        warp_argmax(v, i);
    }
}

// Reduce 64 partials of set j -> argmax (lane 0 of calling warp holds result).
__device__ __forceinline__ void reduce_partials(int j, int b, int lane,
                                                float& v, int& i) {
    v = g_pval[j][b * 64 + lane];
    i = g_pidx[j][b * 64 + lane];
    float v2 = g_pval[j][b * 64 + 32 + lane];
    int   i2 = g_pidx[j][b * 64 + 32 + lane];
    if (v2 > v || (v2 == v && i2 < i)) { v = v2; i = i2; }
    warp_argmax(v, i);
}

// ---------------------------------------------------------------------------
// K1: pack xyz to float4 AND compute first FPS sweep (dist to center 0).
// grid (64, BB) x 256; 1024 pts/block.
// ---------------------------------------------------------------------------
__global__ void __launch_bounds__(256) pack_d0_kernel(const float* __restrict__ pts) {
    const int b = blockIdx.y, chunk = blockIdx.x, tid = threadIdx.x;
    const float* __restrict__ base = pts + (size_t)b * NN * 6;
    const float cx = __ldg(base), cy = __ldg(base + 1), cz = __ldg(base + 2);

    __shared__ float s_val[8];
    __shared__ int   s_idx[8];

    float best = -1.0f;
    int bidx = NN;
    const int p0 = chunk * 1024;
    #pragma unroll
    for (int k = 0; k < 4; k++) {
        int p = p0 + k * 256 + tid;
        const float* q = base + (size_t)p * 6;
        float2 xy = *(const float2*)q;
        float z = q[2];
        g_xyz4[(size_t)b * NN + p] = make_float4(xy.x, xy.y, z, 0.0f);
        float dx = xy.x - cx, dy = xy.y - cy, dz = z - cz;
        float d = dx * dx + dy * dy + dz * dz;
        if (d > best || (d == best && p < bidx)) { best = d; bidx = p; }
    }
    block_argmax256(best, bidx, tid, s_val, s_idx);
    if (tid == 0) {
        g_pval[0][b * 64 + chunk] = best;
        g_pidx[0][b * 64 + chunk] = bidx;
    }
}

// ---------------------------------------------------------------------------
// K2: FPS sweep with S known centers (S=2 or 3). grid (64, BB) x 256.
// Redundantly reduces previous partial sets in-block to recover centers.
// ---------------------------------------------------------------------------
template <int S>
__global__ void __launch_bounds__(256) sweep_kernel(const float* __restrict__ pts) {
    const int b = blockIdx.y, chunk = blockIdx.x, tid = threadIdx.x;
    __shared__ float3 sc[S];
    __shared__ float s_val[8];
    __shared__ int   s_idx[8];

    if (tid == 0) {
        const float* base = pts + (size_t)b * NN * 6;
        sc[0] = make_float3(__ldg(base), __ldg(base + 1), __ldg(base + 2));
    }
    if (tid < 32) {
        #pragma unroll
        for (int j = 0; j < S - 1; j++) {
            float v; int i;
            reduce_partials(j, b, tid, v, i);
            if (tid == 0) {
                float4 c = g_xyz4[(size_t)b * NN + i];
                sc[j + 1] = make_float3(c.x, c.y, c.z);
            }
        }
    }
    __syncthreads();

    float best = -1.0f;
    int bidx = NN;
    const int p0 = chunk * 1024;
    #pragma unroll
    for (int k = 0; k < 4; k++) {
        int p = p0 + k * 256 + tid;
        float4 q = g_xyz4[(size_t)b * NN + p];
        float m = 1e10f;
        #pragma unroll
        for (int t = 0; t < S; t++) {
            float dx = q.x - sc[t].x, dy = q.y - sc[t].y, dz = q.z - sc[t].z;
            float d = dx * dx + dy * dy + dz * dz;
            m = fminf(m, d);
        }
        if (m > best || (m == best && p < bidx)) { best = m; bidx = p; }
    }
    block_argmax256(best, bidx, tid, s_val, s_idx);
    if (tid == 0) {
        g_pval[S - 1][b * 64 + chunk] = best;
        g_pidx[S - 1][b * 64 + chunk] = bidx;
    }
}

// ---------------------------------------------------------------------------
// K3: keep test against all 4 centers -> global bitmask + per-chunk counts.
// grid (32, BB) x 256; 2048 pts/block.
// ---------------------------------------------------------------------------
__global__ void __launch_bounds__(256) keep_kernel(const float* __restrict__ pts) {
    const int b = blockIdx.y, chunk = blockIdx.x, tid = threadIdx.x;
    __shared__ float3 sc[4];
    __shared__ int s_c[8];

    if (tid == 0) {
        const float* base = pts + (size_t)b * NN * 6;
        sc[0] = make_float3(__ldg(base), __ldg(base + 1), __ldg(base + 2));
    }
    if (tid < 32) {
        #pragma unroll
        for (int j = 0; j < 3; j++) {
            float v; int i;
            reduce_partials(j, b, tid, v, i);
            if (tid == 0) {
                float4 c = g_xyz4[(size_t)b * NN + i];
                sc[j + 1] = make_float3(c.x, c.y, c.z);
            }
        }
    }
    __syncthreads();

    const int lane = tid & 31, warp = tid >> 5;
    int cnt = 0;
    const int p0 = chunk * 2048;
    #pragma unroll
    for (int k = 0; k < 8; k++) {
        int p = p0 + k * 256 + tid;
        float4 q = g_xyz4[(size_t)b * NN + p];
        float m = 1e10f;
        #pragma unroll
        for (int t = 0; t < 4; t++) {
            float dx = q.x - sc[t].x, dy = q.y - sc[t].y, dz = q.z - sc[t].z;
            float d = dx * dx + dy * dy + dz * dz;
            m = fminf(m, d);
        }
        bool keep = (sqrtf(m) >= RADIUS);   // == (norm >= 0.2), sqrt monotone
        unsigned w = __ballot_sync(0xffffffffu, keep);
        if (lane == 0) g_bm[b * (NN / 32) + (p >> 5)] = w;
        cnt += keep;
    }
    // block sum
    #pragma unroll
    for (int off = 16; off; off >>= 1) cnt += __shfl_down_sync(0xffffffffu, cnt, off);
    if (lane == 0) s_c[warp] = cnt;
    __syncthreads();
    if (tid == 0) {
        int tot = 0;
        #pragma unroll
        for (int i = 0; i < 8; i++) tot += s_c[i];
        g_cnt[b * 32 + chunk] = tot;
    }
}

// ---------------------------------------------------------------------------
// K4: emit stable kept-index list from bitmask. grid (32, BB) x 64.
// Each thread owns one 32-bit word. Chunk offset computed in-block by
// scanning the batch's 32 chunk counts (tiny, L2-hot) — no separate scan kernel.
// ---------------------------------------------------------------------------
__global__ void __launch_bounds__(64) emit_kernel() {
    const int b = blockIdx.y, chunk = blockIdx.x, tid = threadIdx.x;
    __shared__ int s_tot[2];
    __shared__ int s_chunk_off;

    // warp 1 lane 0..31: scan chunk counts for this batch
    if (tid >= 32) {
        int lane = tid - 32;
        int v = g_cnt[b * 32 + lane];
        int inc = v;
        #pragma unroll
        for (int off = 1; off < 32; off <<= 1) {
            int n = __shfl_up_sync(0xffffffffu, inc, off);
            if (lane >= off) inc += n;
        }
        if (lane == chunk) s_chunk_off = inc - v;
        if (chunk == 0 && lane == 31) g_numvalid[b] = inc;
    }

    const int word = chunk * 64 + tid;               // word within batch
    unsigned m = g_bm[b * (NN / 32) + word];
    int cnt = __popc(m);

    const int lane = tid & 31, warp = tid >> 5;
    int inc = cnt;
    #pragma unroll
    for (int off = 1; off < 32; off <<= 1) {
        int n = __shfl_up_sync(0xffffffffu, inc, off);
        if (lane >= off) inc += n;
    }
    if (lane == 31) s_tot[warp] = inc;
    __syncthreads();
    int off = s_chunk_off + inc - cnt + (warp ? s_tot[0] : 0);

    int* kept = g_kept + (size_t)b * NN;
    const int base = word * 32;
    while (m) {
        int j = __ffs(m) - 1;
        m &= m - 1;
        kept[off++] = base + j;
    }
}

// ---------------------------------------------------------------------------
// K5: gather output: out[b,j] = points[b, kept[j % nv]]  (zeros if nv==0)
// ---------------------------------------------------------------------------
__global__ void __launch_bounds__(256) gather_kernel(const float* __restrict__ pts,
                                                     float* __restrict__ out) {
    int i = blockIdx.x * blockDim.x + threadIdx.x;
    if (i >= BB * NN) return;
    int b = i >> 16;
    int j = i & (NN - 1);
    int nv = g_numvalid[b];
    float2* o = (float2*)(out + (size_t)i * 6);
    if (nv == 0) {
        float2 z = make_float2(0.f, 0.f);
        o[0] = z; o[1] = z; o[2] = z;
        return;
    }
    int k = (j < nv) ? j : (j % nv);
    int src = g_kept[(size_t)b * NN + k];
    const float2* s = (const float2*)(pts + ((size_t)b * NN + src) * 6);
    float2 a0 = s[0], a1 = s[1], a2 = s[2];
    o[0] = a0; o[1] = a1; o[2] = a2;
}

extern "C" void kernel_launch(void* const* d_in, const int* in_sizes, int n_in,
                              void* d_out, int out_size) {
    const float* pts = (const float*)d_in[0];
    float* out = (float*)d_out;
    (void)in_sizes; (void)n_in; (void)out_size;

    pack_d0_kernel<<<dim3(64, BB), 256>>>(pts);
    sweep_kernel<2><<<dim3(64, BB), 256>>>(pts);
    sweep_kernel<3><<<dim3(64, BB), 256>>>(pts);
    keep_kernel<<<dim3(32, BB), 256>>>(pts);
    emit_kernel<<<dim3(32, BB), 64>>>();
    gather_kernel<<<(BB * NN + 255) / 256, 256>>>(pts, out);
}